// round 11
// baseline (speedup 1.0000x reference)
#include <cuda_runtime.h>
#include <math.h>

#define VOCAB 433
#define DMODEL 120
#define BATCH 4096
#define SEQL 16
#define H4 480
#define MTOK (BATCH*SEQL)   // 65536

#define NT_TILES 60          // 480/8 n-tiles (permuted: nt = db*4 + gate)
#define KT_TILES 15          // 120/8 k-tiles
#define WMAT (NT_TILES*KT_TILES*64)   // 57600 floats per packed matrix
#define ROWS 32              // batch rows per LSTM block

// Scratch (static __device__ arrays: allocation-free per harness rules)
__device__ float g_h0[(size_t)MTOK * DMODEL]; // 31.5 MB
__device__ float g_h1[(size_t)MTOK * DMODEL]; // 31.5 MB
__device__ float g_ln[(size_t)MTOK * DMODEL]; // 31.5 MB
__device__ float g_wpk[4 * WMAT];             // Wih0|Whh0|Wih1|Whh1 packed tf32

// Accurate activations (ex2-based; 2^-22.5 max err even under fast-math).
#define LOG2E 1.4426950408889634f
__device__ __forceinline__ float sig_acc(float x) {
    return 1.0f / (1.0f + exp2f(-x * LOG2E));
}
__device__ __forceinline__ float tanh_acc(float x) {
    float e = exp2f(x * (2.0f * LOG2E));
    return 1.0f - 2.0f / (e + 1.0f);
}

__device__ __forceinline__ float tf32r(float x) {
    float r;
    asm("cvt.rna.tf32.f32 %0, %1;" : "=f"(r) : "f"(x));
    return r;
}

// m16n8k8 tf32 tensor-core mma, fp32 accumulate.
__device__ __forceinline__ void mma_tf32(float* d, const unsigned* a,
                                         const unsigned* b) {
    asm volatile(
        "mma.sync.aligned.m16n8k8.row.col.f32.tf32.tf32.f32 "
        "{%0,%1,%2,%3}, {%4,%5,%6,%7}, {%8,%9}, {%0,%1,%2,%3};\n"
        : "+f"(d[0]), "+f"(d[1]), "+f"(d[2]), "+f"(d[3])
        : "r"(a[0]), "r"(a[1]), "r"(a[2]), "r"(a[3]), "r"(b[0]), "r"(b[1]));
}

// ---------------------------------------------------------------------------
// Pack all 4 W[480,120] matrices into gate-permuted per-(n8,k8)-tile
// B-fragment layout (blockIdx.y selects matrix): tile nt = db*4 + q,
// tile row g -> W row q*120 + db*8 + g.
// ---------------------------------------------------------------------------
__global__ void pack_w4(const float* __restrict__ W0, const float* __restrict__ W1,
                        const float* __restrict__ W2, const float* __restrict__ W3,
                        float* __restrict__ Wpk)
{
    int idx = blockIdx.x * 256 + threadIdx.x;     // 0..28799
    if (idx >= NT_TILES * KT_TILES * 32) return;
    const float* W = (blockIdx.y == 0) ? W0 : (blockIdx.y == 1) ? W1
                   : (blockIdx.y == 2) ? W2 : W3;
    float* dst = Wpk + (size_t)blockIdx.y * WMAT;
    int lane = idx & 31, tile = idx >> 5;
    int kt = tile % KT_TILES, nt = tile / KT_TILES;
    int db = nt >> 2, q = nt & 3;
    int g = lane >> 2, tg = lane & 3;
    int row = q * DMODEL + db * 8 + g;
    int k = kt * 8 + tg;
    dst[tile * 64 + lane * 2 + 0] = tf32r(W[row * DMODEL + k]);
    dst[tile * 64 + lane * 2 + 1] = tf32r(W[row * DMODEL + k + 4]);
}

// ---------------------------------------------------------------------------
// Fused LSTM layer: input GEMM + recurrence + cell update, M=32 rows/block,
// 512 threads / 16 warps. Warp = (wm, wn): wm selects the m16-tile (rows
// wm*16..wm*16+15), wn the nt-range (wn<7: d-blocks {2wn,2wn+1}; wn=7: {14}).
// Warps with equal wn and different wm read identical B-fragments -> L1
// dedup; half the blocks of the M=16 version -> half the L2 weight traffic.
// Single-buffered x_s/h_s with two barriers per step (fits 48KB static smem).
// ---------------------------------------------------------------------------
template<bool GATHER>
__global__ __launch_bounds__(512)
void lstm_fused(const float* __restrict__ xin,   // layer1: h0 [B,L,D]
                const int*   __restrict__ xtok,  // layer0: tokens [B,L]
                const float* __restrict__ embed,
                const float* __restrict__ wpk,   // [Wih | Whh] packed
                const float* __restrict__ bih,
                const float* __restrict__ bhh,
                float* __restrict__ hout)
{
    __shared__ float x_s[ROWS][124];
    __shared__ float h_s[ROWS][124];
    __shared__ int   idx_s[ROWS * SEQL];

    const int tid  = threadIdx.x;
    const int wid  = tid >> 5;
    const int lane = tid & 31;
    const int g    = lane >> 2;
    const int tg   = lane & 3;
    const int wn   = wid & 7;
    const int wm   = wid >> 3;
    const int mrow = wm * 16;
    const int b0   = blockIdx.x * ROWS;

    const int dbn = (wn < 7) ? 2 : 1;
    const int db0 = 2 * wn;
    const int nt0 = db0 * 4;
    const int ntn = dbn * 4;

    // Bias regs: bias[jdb][gate][col]
    float bias[2][4][2];
#pragma unroll
    for (int jdb = 0; jdb < 2; jdb++) {
        if (jdb < dbn) {
#pragma unroll
            for (int q = 0; q < 4; q++)
#pragma unroll
                for (int c2 = 0; c2 < 2; c2++) {
                    int d = (db0 + jdb) * 8 + 2 * tg + c2;
                    int row = q * DMODEL + d;
                    bias[jdb][q][c2] = bih[row] + bhh[row];
                }
        }
    }

    if (GATHER)
        idx_s[tid] = xtok[(size_t)(b0 + (tid >> 4)) * SEQL + (tid & 15)];
    __syncthreads();

    // Load x(0) (tf32-rounded): 32 rows x 30 float4 = 960 over 512 threads.
#pragma unroll
    for (int i = 0; i < 2; i++) {
        int flat = tid + 512 * i;
        if (flat < ROWS * 30) {
            int row = flat / 30, c4 = flat % 30;
            const float* src = GATHER
                ? embed + (size_t)idx_s[row * 16] * DMODEL + c4 * 4
                : xin + ((size_t)(b0 + row) * SEQL) * DMODEL + c4 * 4;
            float4 v = *(const float4*)src;
            *(float4*)&x_s[row][c4 * 4] = make_float4(
                tf32r(v.x), tf32r(v.y), tf32r(v.z), tf32r(v.w));
        }
    }
    __syncthreads();

    float c[8];
#pragma unroll
    for (int i = 0; i < 8; i++) c[i] = 0.0f;

#pragma unroll 1
    for (int t = 0; t < SEQL; t++) {
        // Prefetch x(t+1) into regs (LDG latency overlaps mma phase).
        float4 px[2];
        if (t < 15) {
#pragma unroll
            for (int i = 0; i < 2; i++) {
                int flat = tid + 512 * i;
                if (flat < ROWS * 30) {
                    int row = flat / 30, c4 = flat % 30;
                    const float* src = GATHER
                        ? embed + (size_t)idx_s[row * 16 + t + 1] * DMODEL + c4 * 4
                        : xin + ((size_t)(b0 + row) * SEQL + t + 1) * DMODEL + c4 * 4;
                    px[i] = *(const float4*)src;
                }
            }
        }

        float acc[8][4];
#pragma unroll
        for (int j = 0; j < 8; j++)
#pragma unroll
            for (int v = 0; v < 4; v++) acc[j][v] = 0.0f;

        // Input part: x(t) @ Wih^T
#pragma unroll 3
        for (int kt = 0; kt < KT_TILES; kt++) {
            const int k0 = kt * 8;
            unsigned a[4];
            a[0] = __float_as_uint(x_s[mrow + g    ][k0 + tg    ]);
            a[1] = __float_as_uint(x_s[mrow + g + 8][k0 + tg    ]);
            a[2] = __float_as_uint(x_s[mrow + g    ][k0 + tg + 4]);
            a[3] = __float_as_uint(x_s[mrow + g + 8][k0 + tg + 4]);
            const float* bp = wpk + ((size_t)(nt0 * KT_TILES + kt)) * 64 + lane * 2;
#pragma unroll
            for (int j = 0; j < 8; j++) {
                if (j < ntn) {
                    float2 bv = *(const float2*)(bp + j * (KT_TILES * 64));
                    mma_tf32(acc[j], a, (const unsigned*)&bv);
                }
            }
        }
        // Recurrent part: h(t-1) @ Whh^T
        if (t > 0) {
            const float* whh = wpk + WMAT;
#pragma unroll 3
            for (int kt = 0; kt < KT_TILES; kt++) {
                const int k0 = kt * 8;
                unsigned a[4];
                a[0] = __float_as_uint(h_s[mrow + g    ][k0 + tg    ]);
                a[1] = __float_as_uint(h_s[mrow + g + 8][k0 + tg    ]);
                a[2] = __float_as_uint(h_s[mrow + g    ][k0 + tg + 4]);
                a[3] = __float_as_uint(h_s[mrow + g + 8][k0 + tg + 4]);
                const float* bp = whh + ((size_t)(nt0 * KT_TILES + kt)) * 64 + lane * 2;
#pragma unroll
                for (int j = 0; j < 8; j++) {
                    if (j < ntn) {
                        float2 bv = *(const float2*)(bp + j * (KT_TILES * 64));
                        mma_tf32(acc[j], a, (const unsigned*)&bv);
                    }
                }
            }
        }

        __syncthreads();   // all x_s/h_s reads done before overwrite

        // Register-local pointwise cell update (gates i,f,g,o in own regs).
#pragma unroll
        for (int jdb = 0; jdb < 2; jdb++) {
            if (jdb < dbn) {
                const int j0 = jdb * 4;
#pragma unroll
                for (int rs = 0; rs < 2; rs++) {
                    float h2[2];
#pragma unroll
                    for (int cs = 0; cs < 2; cs++) {
                        const int v = rs * 2 + cs;
                        float gi = acc[j0 + 0][v] + bias[jdb][0][cs];
                        float gf = acc[j0 + 1][v] + bias[jdb][1][cs];
                        float gg = acc[j0 + 2][v] + bias[jdb][2][cs];
                        float go = acc[j0 + 3][v] + bias[jdb][3][cs];
                        const int ci = jdb * 4 + rs * 2 + cs;
                        float cn = sig_acc(gf) * c[ci] + sig_acc(gi) * tanh_acc(gg);
                        c[ci] = cn;
                        h2[cs] = sig_acc(go) * tanh_acc(cn);
                    }
                    const int r = mrow + g + rs * 8;
                    const int d = (db0 + jdb) * 8 + 2 * tg;
                    *(float2*)&hout[((size_t)(b0 + r) * SEQL + t) * DMODEL + d] =
                        make_float2(h2[0], h2[1]);
                    h_s[r][d]     = tf32r(h2[0]);
                    h_s[r][d + 1] = tf32r(h2[1]);
                }
            }
        }

        // Stage prefetched x(t+1).
        if (t < 15) {
#pragma unroll
            for (int i = 0; i < 2; i++) {
                int flat = tid + 512 * i;
                if (flat < ROWS * 30) {
                    int row = flat / 30, c4 = flat % 30;
                    *(float4*)&x_s[row][c4 * 4] = make_float4(
                        tf32r(px[i].x), tf32r(px[i].y),
                        tf32r(px[i].z), tf32r(px[i].w));
                }
            }
        }
        __syncthreads();   // new x_s/h_s visible for next step
    }
}

// ---------------------------------------------------------------------------
// Tensor-core GEMM (logits): C[M,N] = A[M,120] @ W[N,120]^T, tf32 mma.
// Block tile 128x128, 256 threads = 8 warps. (unchanged, known-good)
// ---------------------------------------------------------------------------
__global__ __launch_bounds__(256, 2)
void gemm_tc(const float* __restrict__ A,
             const float* __restrict__ W,
             float* __restrict__ C, int N)
{
    __shared__ float As[128][44];
    __shared__ float Ws[128][44];

    const int tid  = threadIdx.x;
    const int wid  = tid >> 5;
    const int lane = tid & 31;
    const int g    = lane >> 2;
    const int tg   = lane & 3;
    const int m0   = blockIdx.x * 128;
    const int n0   = blockIdx.y * 128;
    const int wm   = wid >> 1;
    const int wn   = wid & 1;

    float acc[2][8][4];
#pragma unroll
    for (int mf = 0; mf < 2; mf++)
#pragma unroll
        for (int nf = 0; nf < 8; nf++)
#pragma unroll
            for (int i = 0; i < 4; i++) acc[mf][nf][i] = 0.0f;

#pragma unroll 1
    for (int kt = 0; kt < 3; kt++) {
        const int k0g = kt * 40;
#pragma unroll
        for (int i = 0; i < 5; i++) {
            int flat = tid + i * 256;
            int row = flat / 10, c4 = flat % 10;
            float4 v = *(const float4*)(A + (size_t)(m0 + row) * DMODEL + k0g + c4 * 4);
            As[row][c4*4+0] = tf32r(v.x);
            As[row][c4*4+1] = tf32r(v.y);
            As[row][c4*4+2] = tf32r(v.z);
            As[row][c4*4+3] = tf32r(v.w);
        }
#pragma unroll
        for (int i = 0; i < 5; i++) {
            int flat = tid + i * 256;
            int row = flat / 10, c4 = flat % 10;
            float4 v = make_float4(0.f, 0.f, 0.f, 0.f);
            if (n0 + row < N)
                v = *(const float4*)(W + (size_t)(n0 + row) * DMODEL + k0g + c4 * 4);
            Ws[row][c4*4+0] = tf32r(v.x);
            Ws[row][c4*4+1] = tf32r(v.y);
            Ws[row][c4*4+2] = tf32r(v.z);
            Ws[row][c4*4+3] = tf32r(v.w);
        }
        __syncthreads();

#pragma unroll
        for (int kk = 0; kk < 5; kk++) {
            const int k0 = kk * 8;
            unsigned a[2][4];
#pragma unroll
            for (int mf = 0; mf < 2; mf++) {
                int m = wm * 32 + mf * 16 + g;
                a[mf][0] = __float_as_uint(As[m    ][k0 + tg    ]);
                a[mf][1] = __float_as_uint(As[m + 8][k0 + tg    ]);
                a[mf][2] = __float_as_uint(As[m    ][k0 + tg + 4]);
                a[mf][3] = __float_as_uint(As[m + 8][k0 + tg + 4]);
            }
#pragma unroll
            for (int nf = 0; nf < 8; nf++) {
                unsigned b[2];
                int n = wn * 64 + nf * 8 + g;
                b[0] = __float_as_uint(Ws[n][k0 + tg    ]);
                b[1] = __float_as_uint(Ws[n][k0 + tg + 4]);
                mma_tf32(acc[0][nf], a[0], b);
                mma_tf32(acc[1][nf], a[1], b);
            }
        }
        __syncthreads();
    }

#pragma unroll
    for (int mf = 0; mf < 2; mf++) {
        const int m = m0 + wm * 32 + mf * 16 + g;
#pragma unroll
        for (int nf = 0; nf < 8; nf++) {
            const int n = n0 + wn * 64 + nf * 8 + 2 * tg;
            float* r0 = C + (size_t)m * N;
            float* r1 = C + (size_t)(m + 8) * N;
            if (n < N) {
                r0[n] = acc[mf][nf][0];
                r1[n] = acc[mf][nf][2];
            }
            if (n + 1 < N) {
                r0[n + 1] = acc[mf][nf][1];
                r1[n + 1] = acc[mf][nf][3];
            }
        }
    }
}

// ---------------------------------------------------------------------------
// LayerNorm over D=120: one warp per row (exact fp32).
// ---------------------------------------------------------------------------
__global__ __launch_bounds__(256)
void ln_k(const float* __restrict__ in,
          const float* __restrict__ gamma,
          const float* __restrict__ beta,
          float* __restrict__ out)
{
    const int row  = blockIdx.x * 8 + (threadIdx.x >> 5);
    const int lane = threadIdx.x & 31;
    const float* rp = in + (size_t)row * DMODEL;

    float v[4];
    float s = 0.0f, s2 = 0.0f;
#pragma unroll
    for (int i = 0; i < 4; i++) {
        int d = lane + 32 * i;
        v[i] = (d < DMODEL) ? rp[d] : 0.0f;
        s  += v[i];
        s2 += v[i] * v[i];
    }
#pragma unroll
    for (int off = 16; off > 0; off >>= 1) {
        s  += __shfl_xor_sync(0xffffffffu, s,  off);
        s2 += __shfl_xor_sync(0xffffffffu, s2, off);
    }
    const float mu   = s  * (1.0f / DMODEL);
    const float var  = s2 * (1.0f / DMODEL) - mu * mu;
    const float rstd = rsqrtf(var + 1e-5f);

    float* op = out + (size_t)row * DMODEL;
#pragma unroll
    for (int i = 0; i < 4; i++) {
        int d = lane + 32 * i;
        if (d < DMODEL)
            op[d] = (v[i] - mu) * rstd * gamma[d] + beta[d];
    }
}

// ---------------------------------------------------------------------------
extern "C" void kernel_launch(void* const* d_in, const int* in_sizes, int n_in,
                              void* d_out, int out_size)
{
    const int*   x     = (const int*)  d_in[0];
    const float* embed = (const float*)d_in[1];
    const float* Wih0  = (const float*)d_in[2];
    const float* Whh0  = (const float*)d_in[3];
    const float* bih0  = (const float*)d_in[4];
    const float* bhh0  = (const float*)d_in[5];
    const float* Wih1  = (const float*)d_in[6];
    const float* Whh1  = (const float*)d_in[7];
    const float* bih1  = (const float*)d_in[8];
    const float* bhh1  = (const float*)d_in[9];
    const float* gamma = (const float*)d_in[10];
    const float* beta  = (const float*)d_in[11];
    float* out = (float*)d_out;

    float *h0, *h1, *ln, *wpk;
    cudaGetSymbolAddress((void**)&h0,  g_h0);
    cudaGetSymbolAddress((void**)&h1,  g_h1);
    cudaGetSymbolAddress((void**)&ln,  g_ln);
    cudaGetSymbolAddress((void**)&wpk, g_wpk);

    const int packGrid = (NT_TILES * KT_TILES * 32 + 255) / 256;
    dim3 g433(MTOK / 128, (VOCAB + 127) / 128);  // (512, 4)

    // Pack all four weight matrices in one launch.
    pack_w4<<<dim3(packGrid, 4), 256>>>(Wih0, Whh0, Wih1, Whh1, wpk);

    // Layer 0: fused embed-gather + input GEMM + recurrence (M=32/block).
    lstm_fused<true ><<<BATCH / ROWS, 512>>>(nullptr, x, embed, wpk,
                                             bih0, bhh0, h0);
    // Layer 1: fused (input = h0).
    lstm_fused<false><<<BATCH / ROWS, 512>>>(h0, nullptr, nullptr, wpk + 2 * WMAT,
                                             bih1, bhh1, h1);
    // LayerNorm
    ln_k<<<MTOK / 8, 256>>>(h1, gamma, beta, ln);
    // Tied-embedding head: logits = ln @ embed^T
    gemm_tc<<<g433, 256>>>(ln, embed, out, VOCAB);
}

// round 13
// speedup vs baseline: 2.3195x; 2.3195x over previous
#include <cuda_runtime.h>
#include <cuda_fp16.h>
#include <math.h>

#define VOCAB 433
#define DMODEL 120
#define BATCH 4096
#define SEQL 16
#define H4 480
#define MTOK (BATCH*SEQL)   // 65536

#define NT_TILES 60          // 480/8 n-tiles (permuted: nt = db*4 + gate)
#define KT16 8               // k16-tiles after padding K=120 -> 128
#define WMAT_U4 (NT_TILES*4*32)       // uint4 per packed matrix (7680)
#define ROWS 16              // batch rows per LSTM block

// Scratch (static __device__ arrays: allocation-free per harness rules)
__device__ float g_h0[(size_t)MTOK * DMODEL]; // 31.5 MB
__device__ float g_h1[(size_t)MTOK * DMODEL]; // 31.5 MB
__device__ float g_ln[(size_t)MTOK * DMODEL]; // 31.5 MB
__device__ uint4 g_wpk[4 * WMAT_U4];          // Wih0|Whh0|Wih1|Whh1 fp16-packed

// Accurate activations (ex2-based; 2^-22.5 max err even under fast-math).
#define LOG2E 1.4426950408889634f
__device__ __forceinline__ float sig_acc(float x) {
    return 1.0f / (1.0f + exp2f(-x * LOG2E));
}
__device__ __forceinline__ float tanh_acc(float x) {
    float e = exp2f(x * (2.0f * LOG2E));
    return 1.0f - 2.0f / (e + 1.0f);
}

// m16n8k16 fp16 tensor-core mma, fp32 accumulate. fp16 mantissa (1+10) ==
// tf32 mantissa, so operand quantization error matches the validated tf32
// configuration (rel_err 2.8e-4) while halving instruction count.
__device__ __forceinline__ void mma_f16(float* d, const unsigned* a,
                                        unsigned b0, unsigned b1) {
    asm volatile(
        "mma.sync.aligned.m16n8k16.row.col.f32.f16.f16.f32 "
        "{%0,%1,%2,%3}, {%4,%5,%6,%7}, {%8,%9}, {%0,%1,%2,%3};\n"
        : "+f"(d[0]), "+f"(d[1]), "+f"(d[2]), "+f"(d[3])
        : "r"(a[0]), "r"(a[1]), "r"(a[2]), "r"(a[3]), "r"(b0), "r"(b1));
}

__device__ __forceinline__ unsigned h2u(float x, float y) {
    __half2 h = __floats2half2_rn(x, y);
    return *(unsigned*)&h;
}

// ---------------------------------------------------------------------------
// Pack 4x W[480,120] into gate-permuted fp16 B-fragment layout for m16n8k16,
// kt-paired so one LDG.128 fetches two k16-tiles:
// uint4 at ((mat*60+nt)*4 + ktp)*32 + lane = {b0(kt=2ktp), b1(kt=2ktp),
//                                             b0(kt=2ktp+1), b1(kt=2ktp+1)}
// b0 = {W[row][k0], W[row][k0+1]}, b1 = {W[row][k0+8], W[row][k0+9]},
// k0 = kt*16 + 2*tg, row = q*120 + db*8 + g (nt = db*4 + q). k>=120 -> 0.
// ---------------------------------------------------------------------------
__global__ void pack_wf16(const float* __restrict__ W0, const float* __restrict__ W1,
                          const float* __restrict__ W2, const float* __restrict__ W3,
                          unsigned* __restrict__ Wpk)
{
    int idx = blockIdx.x * 256 + threadIdx.x;    // 0..61439
    if (idx >= 4 * NT_TILES * KT16 * 32) return;
    int mat  = idx / (NT_TILES * KT16 * 32);
    int rem  = idx % (NT_TILES * KT16 * 32);
    int lane = rem & 31, tile = rem >> 5;
    int kt = tile % KT16, nt = tile / KT16;
    const float* W = (mat == 0) ? W0 : (mat == 1) ? W1 : (mat == 2) ? W2 : W3;
    int db = nt >> 2, q = nt & 3;
    int g = lane >> 2, tg = lane & 3;
    int row = q * DMODEL + db * 8 + g;
    int k0 = kt * 16 + 2 * tg;
    const float* wr = W + (size_t)row * DMODEL;
    float v0 = (k0     < DMODEL) ? wr[k0]     : 0.0f;
    float v1 = (k0 + 1 < DMODEL) ? wr[k0 + 1] : 0.0f;
    float v2 = (k0 + 8 < DMODEL) ? wr[k0 + 8] : 0.0f;
    float v3 = (k0 + 9 < DMODEL) ? wr[k0 + 9] : 0.0f;
    int ktp = kt >> 1, half_sel = kt & 1;
    size_t base = (((size_t)(mat * NT_TILES + nt) * 4 + ktp) * 32 + lane) * 4
                + half_sel * 2;
    Wpk[base]     = h2u(v0, v1);
    Wpk[base + 1] = h2u(v2, v3);
}

// ---------------------------------------------------------------------------
// Fused LSTM layer (fp16 mma): input GEMM + recurrence + cell update.
// Block = 16 batch rows x 16 timesteps, 256 threads / 8 warps (R10 shape:
// ping-pong x_s/h_s, ONE barrier/step, 2 blocks/SM). Warp w<7 owns d-blocks
// {2w,2w+1} (8 n-tiles), warp 7 owns {14} -> gates i,f,g,o register-local.
// Per warp-step: 64 LDG.128 (weights) + 128 mma + 64 LDS (~2.3x fewer issue
// slots than the tf32/k8 version -- the kernel is issue-count bound).
// ---------------------------------------------------------------------------
template<bool GATHER>
__global__ __launch_bounds__(256)
void lstm_fused(const float* __restrict__ xin,   // layer1: h0 [B,L,D]
                const int*   __restrict__ xtok,  // layer0: tokens [B,L]
                const float* __restrict__ embed,
                const uint4* __restrict__ wih4,  // packed Wih (this layer)
                const uint4* __restrict__ whh4,  // packed Whh (this layer)
                const float* __restrict__ bih,
                const float* __restrict__ bhh,
                float* __restrict__ hout)
{
    __shared__ __half2 x_s[2][ROWS][68];   // 60 data half2 + 4 zero-pad + 4
    __shared__ __half2 h_s[2][ROWS][68];
    __shared__ int     idx_s[ROWS * SEQL];

    const int tid  = threadIdx.x;
    const int wid  = tid >> 5;
    const int lane = tid & 31;
    const int g    = lane >> 2;
    const int tg   = lane & 3;
    const int b0   = blockIdx.x * ROWS;

    const int dbn = (wid < 7) ? 2 : 1;
    const int db0 = 2 * wid;
    const int nt0 = db0 * 4;
    const int ntn = dbn * 4;

    // Bias regs: bias[jdb][gate][col]
    float bias[2][4][2];
#pragma unroll
    for (int jdb = 0; jdb < 2; jdb++) {
        if (jdb < dbn) {
#pragma unroll
            for (int q = 0; q < 4; q++)
#pragma unroll
                for (int c2 = 0; c2 < 2; c2++) {
                    int d = (db0 + jdb) * 8 + 2 * tg + c2;
                    bias[jdb][q][c2] = bih[q * DMODEL + d] + bhh[q * DMODEL + d];
                }
        }
    }

    if (GATHER)
        idx_s[tid] = xtok[(size_t)(b0 + (tid >> 4)) * SEQL + (tid & 15)];

    // Zero the k-padding columns (half2 cols 60..63 = halves 120..127) of all
    // four buffers; 2 arr x 2 buf x 16 rows x 4 cols = 256 slots, one/thread.
    {
        int arr = tid >> 7, buf = (tid >> 6) & 1, row = (tid >> 2) & 15;
        int col = 60 + (tid & 3);
        if (arr == 0) x_s[buf][row][col] = __floats2half2_rn(0.0f, 0.0f);
        else          h_s[buf][row][col] = __floats2half2_rn(0.0f, 0.0f);
    }
    __syncthreads();

    // Load x(0): 16 rows x 30 float4 = 480 over 256 threads.
#pragma unroll
    for (int i = 0; i < 2; i++) {
        int flat = tid + 256 * i;
        if (flat < ROWS * 30) {
            int row = flat / 30, c4 = flat % 30;
            const float* src = GATHER
                ? embed + (size_t)idx_s[row * 16] * DMODEL + c4 * 4
                : xin + ((size_t)(b0 + row) * SEQL) * DMODEL + c4 * 4;
            float4 v = *(const float4*)src;
            x_s[0][row][c4 * 2]     = __floats2half2_rn(v.x, v.y);
            x_s[0][row][c4 * 2 + 1] = __floats2half2_rn(v.z, v.w);
        }
    }
    __syncthreads();

    float c[8];
#pragma unroll
    for (int i = 0; i < 8; i++) c[i] = 0.0f;

#pragma unroll 1
    for (int t = 0; t < SEQL; t++) {
        const int cur = t & 1, nxt = cur ^ 1;

        // Prefetch x(t+1) into regs (LDG latency overlaps mma phase).
        float4 px[2];
        if (t < 15) {
#pragma unroll
            for (int i = 0; i < 2; i++) {
                int flat = tid + 256 * i;
                if (flat < ROWS * 30) {
                    int row = flat / 30, c4 = flat % 30;
                    const float* src = GATHER
                        ? embed + (size_t)idx_s[row * 16 + t + 1] * DMODEL + c4 * 4
                        : xin + ((size_t)(b0 + row) * SEQL + t + 1) * DMODEL + c4 * 4;
                    px[i] = *(const float4*)src;
                }
            }
        }

        float acc[8][4];
#pragma unroll
        for (int j = 0; j < 8; j++)
#pragma unroll
            for (int v = 0; v < 4; v++) acc[j][v] = 0.0f;

        // Input part: x(t) @ Wih^T   (4 ktp x [8 LDS + 8 LDG.128 + 16 mma])
#pragma unroll
        for (int ktp = 0; ktp < 4; ktp++) {
            const int cb = ktp * 16;           // half2 col base of kt=2*ktp
            unsigned a0[4], a1[4];
            a0[0] = *(const unsigned*)&x_s[cur][g    ][cb + tg    ];
            a0[1] = *(const unsigned*)&x_s[cur][g + 8][cb + tg    ];
            a0[2] = *(const unsigned*)&x_s[cur][g    ][cb + tg + 4];
            a0[3] = *(const unsigned*)&x_s[cur][g + 8][cb + tg + 4];
            a1[0] = *(const unsigned*)&x_s[cur][g    ][cb + 8 + tg    ];
            a1[1] = *(const unsigned*)&x_s[cur][g + 8][cb + 8 + tg    ];
            a1[2] = *(const unsigned*)&x_s[cur][g    ][cb + 8 + tg + 4];
            a1[3] = *(const unsigned*)&x_s[cur][g + 8][cb + 8 + tg + 4];
#pragma unroll
            for (int j = 0; j < 8; j++) {
                if (j < ntn) {
                    uint4 bv = wih4[((nt0 + j) * 4 + ktp) * 32 + lane];
                    mma_f16(acc[j], a0, bv.x, bv.y);
                    mma_f16(acc[j], a1, bv.z, bv.w);
                }
            }
        }
        // Recurrent part: h(t-1) @ Whh^T
        if (t > 0) {
#pragma unroll
            for (int ktp = 0; ktp < 4; ktp++) {
                const int cb = ktp * 16;
                unsigned a0[4], a1[4];
                a0[0] = *(const unsigned*)&h_s[cur][g    ][cb + tg    ];
                a0[1] = *(const unsigned*)&h_s[cur][g + 8][cb + tg    ];
                a0[2] = *(const unsigned*)&h_s[cur][g    ][cb + tg + 4];
                a0[3] = *(const unsigned*)&h_s[cur][g + 8][cb + tg + 4];
                a1[0] = *(const unsigned*)&h_s[cur][g    ][cb + 8 + tg    ];
                a1[1] = *(const unsigned*)&h_s[cur][g + 8][cb + 8 + tg    ];
                a1[2] = *(const unsigned*)&h_s[cur][g    ][cb + 8 + tg + 4];
                a1[3] = *(const unsigned*)&h_s[cur][g + 8][cb + 8 + tg + 4];
#pragma unroll
                for (int j = 0; j < 8; j++) {
                    if (j < ntn) {
                        uint4 bv = whh4[((nt0 + j) * 4 + ktp) * 32 + lane];
                        mma_f16(acc[j], a0, bv.x, bv.y);
                        mma_f16(acc[j], a1, bv.z, bv.w);
                    }
                }
            }
        }

        // Register-local pointwise cell update (gate order i, f, g, o).
#pragma unroll
        for (int jdb = 0; jdb < 2; jdb++) {
            if (jdb < dbn) {
                const int j0 = jdb * 4;
#pragma unroll
                for (int rs = 0; rs < 2; rs++) {
                    float h2v[2];
#pragma unroll
                    for (int cs = 0; cs < 2; cs++) {
                        const int v = rs * 2 + cs;
                        float gi = acc[j0 + 0][v] + bias[jdb][0][cs];
                        float gf = acc[j0 + 1][v] + bias[jdb][1][cs];
                        float gg = acc[j0 + 2][v] + bias[jdb][2][cs];
                        float go = acc[j0 + 3][v] + bias[jdb][3][cs];
                        const int ci = jdb * 4 + rs * 2 + cs;
                        float cn = sig_acc(gf) * c[ci] + sig_acc(gi) * tanh_acc(gg);
                        c[ci] = cn;
                        h2v[cs] = sig_acc(go) * tanh_acc(cn);
                    }
                    const int r = g + rs * 8;
                    const int d = (db0 + jdb) * 8 + 2 * tg;
                    *(float2*)&hout[((size_t)(b0 + r) * SEQL + t) * DMODEL + d] =
                        make_float2(h2v[0], h2v[1]);      // exact fp32 h
                    h_s[nxt][r][d >> 1] =                 // fp16 mma operand
                        __floats2half2_rn(h2v[0], h2v[1]);
                }
            }
        }

        // Stage prefetched x(t+1).
        if (t < 15) {
#pragma unroll
            for (int i = 0; i < 2; i++) {
                int flat = tid + 256 * i;
                if (flat < ROWS * 30) {
                    int row = flat / 30, c4 = flat % 30;
                    x_s[nxt][row][c4 * 2]     = __floats2half2_rn(px[i].x, px[i].y);
                    x_s[nxt][row][c4 * 2 + 1] = __floats2half2_rn(px[i].z, px[i].w);
                }
            }
        }
        __syncthreads();
    }
}

// ---------------------------------------------------------------------------
// fp16 tensor-core GEMM (logits): C[M,N] = A[M,120] @ W[N,120]^T, fp32 acc.
// Block tile 128x128, 256 thr / 8 warps (4 m-warps x 2 n-warps). K padded to
// 128, staged in 2 smem chunks of 64. smem stride 36 half2 (36%32==4 ->
// frag pattern 4g+tg covers 32 banks, conflict-free).
// ---------------------------------------------------------------------------
__global__ __launch_bounds__(256, 2)
void gemm_f16(const float* __restrict__ A,
              const float* __restrict__ W,
              float* __restrict__ C, int N)
{
    __shared__ __half2 As2[128][36];
    __shared__ __half2 Ws2[128][36];

    const int tid  = threadIdx.x;
    const int wid  = tid >> 5;
    const int lane = tid & 31;
    const int g    = lane >> 2;
    const int tg   = lane & 3;
    const int m0   = blockIdx.x * 128;
    const int n0   = blockIdx.y * 128;
    const int wm   = wid >> 1;
    const int wn   = wid & 1;

    float acc[2][8][4];
#pragma unroll
    for (int mf = 0; mf < 2; mf++)
#pragma unroll
        for (int nf = 0; nf < 8; nf++)
#pragma unroll
            for (int i = 0; i < 4; i++) acc[mf][nf][i] = 0.0f;

#pragma unroll 1
    for (int ks = 0; ks < 2; ks++) {
        // Load 128 rows x 64 halves (16 float4/row): 2048 float4, 8/thread.
#pragma unroll
        for (int i = 0; i < 8; i++) {
            int flat = tid + i * 256;
            int row = flat >> 4, c4 = flat & 15;
            int k = ks * 64 + c4 * 4;
            float4 v = make_float4(0.f, 0.f, 0.f, 0.f);
            if (k < DMODEL)
                v = *(const float4*)(A + (size_t)(m0 + row) * DMODEL + k);
            As2[row][c4 * 2]     = __floats2half2_rn(v.x, v.y);
            As2[row][c4 * 2 + 1] = __floats2half2_rn(v.z, v.w);
        }
#pragma unroll
        for (int i = 0; i < 8; i++) {
            int flat = tid + i * 256;
            int row = flat >> 4, c4 = flat & 15;
            int k = ks * 64 + c4 * 4;
            float4 v = make_float4(0.f, 0.f, 0.f, 0.f);
            if (k < DMODEL && n0 + row < N)
                v = *(const float4*)(W + (size_t)(n0 + row) * DMODEL + k);
            Ws2[row][c4 * 2]     = __floats2half2_rn(v.x, v.y);
            Ws2[row][c4 * 2 + 1] = __floats2half2_rn(v.z, v.w);
        }
        __syncthreads();

#pragma unroll
        for (int kt = 0; kt < 4; kt++) {
            const int cb = kt * 8;
            unsigned a[2][4];
#pragma unroll
            for (int mf = 0; mf < 2; mf++) {
                int m = wm * 32 + mf * 16 + g;
                a[mf][0] = *(const unsigned*)&As2[m    ][cb + tg    ];
                a[mf][1] = *(const unsigned*)&As2[m + 8][cb + tg    ];
                a[mf][2] = *(const unsigned*)&As2[m    ][cb + tg + 4];
                a[mf][3] = *(const unsigned*)&As2[m + 8][cb + tg + 4];
            }
#pragma unroll
            for (int nf = 0; nf < 8; nf++) {
                int n = wn * 64 + nf * 8 + g;
                unsigned b0 = *(const unsigned*)&Ws2[n][cb + tg    ];
                unsigned b1 = *(const unsigned*)&Ws2[n][cb + tg + 4];
                mma_f16(acc[0][nf], a[0], b0, b1);
                mma_f16(acc[1][nf], a[1], b0, b1);
            }
        }
        __syncthreads();
    }

#pragma unroll
    for (int mf = 0; mf < 2; mf++) {
        const int m = m0 + wm * 32 + mf * 16 + g;
#pragma unroll
        for (int nf = 0; nf < 8; nf++) {
            const int n = n0 + wn * 64 + nf * 8 + 2 * tg;
            float* r0 = C + (size_t)m * N;
            float* r1 = C + (size_t)(m + 8) * N;
            if (n < N) {
                r0[n] = acc[mf][nf][0];
                r1[n] = acc[mf][nf][2];
            }
            if (n + 1 < N) {
                r0[n + 1] = acc[mf][nf][1];
                r1[n + 1] = acc[mf][nf][3];
            }
        }
    }
}

// ---------------------------------------------------------------------------
// LayerNorm over D=120: one warp per row (exact fp32).
// ---------------------------------------------------------------------------
__global__ __launch_bounds__(256)
void ln_k(const float* __restrict__ in,
          const float* __restrict__ gamma,
          const float* __restrict__ beta,
          float* __restrict__ out)
{
    const int row  = blockIdx.x * 8 + (threadIdx.x >> 5);
    const int lane = threadIdx.x & 31;
    const float* rp = in + (size_t)row * DMODEL;

    float v[4];
    float s = 0.0f, s2 = 0.0f;
#pragma unroll
    for (int i = 0; i < 4; i++) {
        int d = lane + 32 * i;
        v[i] = (d < DMODEL) ? rp[d] : 0.0f;
        s  += v[i];
        s2 += v[i] * v[i];
    }
#pragma unroll
    for (int off = 16; off > 0; off >>= 1) {
        s  += __shfl_xor_sync(0xffffffffu, s,  off);
        s2 += __shfl_xor_sync(0xffffffffu, s2, off);
    }
    const float mu   = s  * (1.0f / DMODEL);
    const float var  = s2 * (1.0f / DMODEL) - mu * mu;
    const float rstd = rsqrtf(var + 1e-5f);

    float* op = out + (size_t)row * DMODEL;
#pragma unroll
    for (int i = 0; i < 4; i++) {
        int d = lane + 32 * i;
        if (d < DMODEL)
            op[d] = (v[i] - mu) * rstd * gamma[d] + beta[d];
    }
}

// ---------------------------------------------------------------------------
extern "C" void kernel_launch(void* const* d_in, const int* in_sizes, int n_in,
                              void* d_out, int out_size)
{
    const int*   x     = (const int*)  d_in[0];
    const float* embed = (const float*)d_in[1];
    const float* Wih0  = (const float*)d_in[2];
    const float* Whh0  = (const float*)d_in[3];
    const float* bih0  = (const float*)d_in[4];
    const float* bhh0  = (const float*)d_in[5];
    const float* Wih1  = (const float*)d_in[6];
    const float* Whh1  = (const float*)d_in[7];
    const float* bih1  = (const float*)d_in[8];
    const float* bhh1  = (const float*)d_in[9];
    const float* gamma = (const float*)d_in[10];
    const float* beta  = (const float*)d_in[11];
    float* out = (float*)d_out;

    float *h0, *h1, *ln;
    uint4* wpk;
    cudaGetSymbolAddress((void**)&h0,  g_h0);
    cudaGetSymbolAddress((void**)&h1,  g_h1);
    cudaGetSymbolAddress((void**)&ln,  g_ln);
    cudaGetSymbolAddress((void**)&wpk, g_wpk);

    const int packGrid = (4 * NT_TILES * KT16 * 32 + 255) / 256;  // 240
    dim3 g433(MTOK / 128, (VOCAB + 127) / 128);  // (512, 4)

    // Pack all four weight matrices (fp16, kt-paired fragment layout).
    pack_wf16<<<packGrid, 256>>>(Wih0, Whh0, Wih1, Whh1, (unsigned*)wpk);

    // Layer 0: fused embed-gather + input GEMM + recurrence.
    lstm_fused<true ><<<BATCH / ROWS, 256>>>(nullptr, x, embed,
                                             wpk, wpk + WMAT_U4,
                                             bih0, bhh0, h0);
    // Layer 1: fused (input = h0).
    lstm_fused<false><<<BATCH / ROWS, 256>>>(h0, nullptr, nullptr,
                                             wpk + 2 * WMAT_U4, wpk + 3 * WMAT_U4,
                                             bih1, bhh1, h1);
    // LayerNorm
    ln_k<<<MTOK / 8, 256>>>(h1, gamma, beta, ln);
    // Tied-embedding head: logits = ln @ embed^T
    gemm_f16<<<g433, 256>>>(ln, embed, out, VOCAB);
}

// round 14
// speedup vs baseline: 2.9304x; 1.2634x over previous
#include <cuda_runtime.h>
#include <cuda_fp16.h>
#include <math.h>

#define VOCAB 433
#define DMODEL 120
#define BATCH 4096
#define SEQL 16
#define H4 480
#define MTOK (BATCH*SEQL)   // 65536
#define DPAD 128             // fp16 handoff row stride (zero-padded 120->128)

#define NT_TILES 60          // 480/8 n-tiles (permuted: nt = db*4 + gate)
#define KT16 8               // k16-tiles after padding K=120 -> 128
#define WMAT_U4 (NT_TILES*4*32)       // uint4 per packed matrix (7680)
#define ROWS 16              // batch rows per LSTM block

// Scratch (static __device__ arrays: allocation-free; zero-initialized at
// module load -- padding columns 120..127 of the fp16 buffers stay zero
// forever since kernels only ever write cols < 120).
__device__ __half g_h0[(size_t)MTOK * DPAD];  // 16 MB  (layer0 h, fp16 operand)
__device__ float  g_h1[(size_t)MTOK * DMODEL];// 31.5 MB (layer1 h, fp32 for LN)
__device__ __half g_lnh[(size_t)MTOK * DPAD]; // 16 MB  (LN out, fp16 operand)
__device__ uint4  g_wpk[4 * WMAT_U4];         // Wih0|Whh0|Wih1|Whh1 fp16-packed

// Accurate activations (ex2-based; 2^-22.5 max err even under fast-math).
#define LOG2E 1.4426950408889634f
__device__ __forceinline__ float sig_acc(float x) {
    return 1.0f / (1.0f + exp2f(-x * LOG2E));
}
__device__ __forceinline__ float tanh_acc(float x) {
    float e = exp2f(x * (2.0f * LOG2E));
    return 1.0f - 2.0f / (e + 1.0f);
}

// m16n8k16 fp16 tensor-core mma, fp32 accumulate.
__device__ __forceinline__ void mma_f16(float* d, const unsigned* a,
                                        unsigned b0, unsigned b1) {
    asm volatile(
        "mma.sync.aligned.m16n8k16.row.col.f32.f16.f16.f32 "
        "{%0,%1,%2,%3}, {%4,%5,%6,%7}, {%8,%9}, {%0,%1,%2,%3};\n"
        : "+f"(d[0]), "+f"(d[1]), "+f"(d[2]), "+f"(d[3])
        : "r"(a[0]), "r"(a[1]), "r"(a[2]), "r"(a[3]), "r"(b0), "r"(b1));
}

__device__ __forceinline__ unsigned h2u(float x, float y) {
    __half2 h = __floats2half2_rn(x, y);
    return *(unsigned*)&h;
}

// ---------------------------------------------------------------------------
// Pack 4x W[480,120] into gate-permuted fp16 B-fragment layout for m16n8k16,
// kt-paired so one LDG.128 fetches two k16-tiles. (unchanged, known-good)
// ---------------------------------------------------------------------------
__global__ void pack_wf16(const float* __restrict__ W0, const float* __restrict__ W1,
                          const float* __restrict__ W2, const float* __restrict__ W3,
                          unsigned* __restrict__ Wpk)
{
    int idx = blockIdx.x * 256 + threadIdx.x;    // 0..61439
    if (idx >= 4 * NT_TILES * KT16 * 32) return;
    int mat  = idx / (NT_TILES * KT16 * 32);
    int rem  = idx % (NT_TILES * KT16 * 32);
    int lane = rem & 31, tile = rem >> 5;
    int kt = tile % KT16, nt = tile / KT16;
    const float* W = (mat == 0) ? W0 : (mat == 1) ? W1 : (mat == 2) ? W2 : W3;
    int db = nt >> 2, q = nt & 3;
    int g = lane >> 2, tg = lane & 3;
    int row = q * DMODEL + db * 8 + g;
    int k0 = kt * 16 + 2 * tg;
    const float* wr = W + (size_t)row * DMODEL;
    float v0 = (k0     < DMODEL) ? wr[k0]     : 0.0f;
    float v1 = (k0 + 1 < DMODEL) ? wr[k0 + 1] : 0.0f;
    float v2 = (k0 + 8 < DMODEL) ? wr[k0 + 8] : 0.0f;
    float v3 = (k0 + 9 < DMODEL) ? wr[k0 + 9] : 0.0f;
    int ktp = kt >> 1, half_sel = kt & 1;
    size_t base = (((size_t)(mat * NT_TILES + nt) * 4 + ktp) * 32 + lane) * 4
                + half_sel * 2;
    Wpk[base]     = h2u(v0, v1);
    Wpk[base + 1] = h2u(v2, v3);
}

// ---------------------------------------------------------------------------
// Fused LSTM layer (fp16 mma). Block = 16 rows x 16 steps, 256 thr / 8 warps.
// __launch_bounds__(256,2): <=128 regs -> 2 blocks/SM -> 256 blocks in ONE
// wave with 16 warps/SM (the R13 kernel likely spilled past 128 and ran
// 1 block/SM in 2 waves). Bias lives in smem (saves 16 regs).
// L0: input = embed gather (fp32->fp16), output = fp16 padded [.,128]
//     (h0 is consumed only as layer1's fp16 mma operand -> identical math).
// L1: input = fp16 padded h0 (raw uint4 stage, no cvt), output = fp32 h1.
// ---------------------------------------------------------------------------
template<bool L0>
__global__ __launch_bounds__(256, 2)
void lstm_fused(const __half* __restrict__ xin_h,  // L1 input [B*L][128] fp16
                const int*    __restrict__ xtok,   // L0 tokens [B,L]
                const float*  __restrict__ embed,
                const uint4*  __restrict__ wih4,
                const uint4*  __restrict__ whh4,
                const float*  __restrict__ bih,
                const float*  __restrict__ bhh,
                __half* __restrict__ hout_h,       // L0 out
                float*  __restrict__ hout_f)       // L1 out
{
    __shared__ __half2 x_s[2][ROWS][68];   // 60 data half2 + 4 zero-pad + 4
    __shared__ __half2 h_s[2][ROWS][68];
    __shared__ float   bias_s[H4];
    __shared__ int     idx_s[ROWS * SEQL];

    const int tid  = threadIdx.x;
    const int wid  = tid >> 5;
    const int lane = tid & 31;
    const int g    = lane >> 2;
    const int tg   = lane & 3;
    const int b0   = blockIdx.x * ROWS;

    const int dbn = (wid < 7) ? 2 : 1;
    const int db0 = 2 * wid;
    const int nt0 = db0 * 4;
    const int ntn = dbn * 4;

    // Combined bias to smem.
#pragma unroll
    for (int i = 0; i < 2; i++) {
        int idx = tid + 256 * i;
        if (idx < H4) bias_s[idx] = bih[idx] + bhh[idx];
    }

    if (L0)
        idx_s[tid] = xtok[(size_t)(b0 + (tid >> 4)) * SEQL + (tid & 15)];

    // Zero k-padding cols (half2 60..63) of both ping-pong x_s/h_s buffers.
    {
        int arr = tid >> 7, buf = (tid >> 6) & 1, row = (tid >> 2) & 15;
        int col = 60 + (tid & 3);
        if (arr == 0) x_s[buf][row][col] = __floats2half2_rn(0.0f, 0.0f);
        else          h_s[buf][row][col] = __floats2half2_rn(0.0f, 0.0f);
    }
    __syncthreads();

    // Load x(0).
    if (L0) {
#pragma unroll
        for (int i = 0; i < 2; i++) {
            int flat = tid + 256 * i;
            if (flat < ROWS * 30) {
                int row = flat / 30, c4 = flat % 30;
                const float* src = embed + (size_t)idx_s[row * 16] * DMODEL + c4 * 4;
                float4 v = *(const float4*)src;
                x_s[0][row][c4 * 2]     = __floats2half2_rn(v.x, v.y);
                x_s[0][row][c4 * 2 + 1] = __floats2half2_rn(v.z, v.w);
            }
        }
    } else {
        int row = tid >> 4, u = tid & 15;   // 16 rows x 16 uint4
        uint4 v = *(const uint4*)(xin_h + ((size_t)(b0 + row) * SEQL) * DPAD + u * 8);
        *(uint4*)&x_s[0][row][u * 4] = v;
    }
    __syncthreads();

    float c[8];
#pragma unroll
    for (int i = 0; i < 8; i++) c[i] = 0.0f;

#pragma unroll 1
    for (int t = 0; t < SEQL; t++) {
        const int cur = t & 1, nxt = cur ^ 1;

        // Prefetch x(t+1) into regs (LDG latency overlaps mma phase).
        float4 pxf[2];
        uint4  pxh;
        if (t < 15) {
            if (L0) {
#pragma unroll
                for (int i = 0; i < 2; i++) {
                    int flat = tid + 256 * i;
                    if (flat < ROWS * 30) {
                        int row = flat / 30, c4 = flat % 30;
                        pxf[i] = *(const float4*)(embed
                            + (size_t)idx_s[row * 16 + t + 1] * DMODEL + c4 * 4);
                    }
                }
            } else {
                int row = tid >> 4, u = tid & 15;
                pxh = *(const uint4*)(xin_h
                    + ((size_t)(b0 + row) * SEQL + t + 1) * DPAD + u * 8);
            }
        }

        float acc[8][4];
#pragma unroll
        for (int j = 0; j < 8; j++)
#pragma unroll
            for (int v = 0; v < 4; v++) acc[j][v] = 0.0f;

        // Input part: x(t) @ Wih^T
#pragma unroll
        for (int ktp = 0; ktp < 4; ktp++) {
            const int cb = ktp * 16;
            unsigned a0[4], a1[4];
            a0[0] = *(const unsigned*)&x_s[cur][g    ][cb + tg    ];
            a0[1] = *(const unsigned*)&x_s[cur][g + 8][cb + tg    ];
            a0[2] = *(const unsigned*)&x_s[cur][g    ][cb + tg + 4];
            a0[3] = *(const unsigned*)&x_s[cur][g + 8][cb + tg + 4];
            a1[0] = *(const unsigned*)&x_s[cur][g    ][cb + 8 + tg    ];
            a1[1] = *(const unsigned*)&x_s[cur][g + 8][cb + 8 + tg    ];
            a1[2] = *(const unsigned*)&x_s[cur][g    ][cb + 8 + tg + 4];
            a1[3] = *(const unsigned*)&x_s[cur][g + 8][cb + 8 + tg + 4];
#pragma unroll
            for (int j = 0; j < 8; j++) {
                if (j < ntn) {
                    uint4 bv = wih4[((nt0 + j) * 4 + ktp) * 32 + lane];
                    mma_f16(acc[j], a0, bv.x, bv.y);
                    mma_f16(acc[j], a1, bv.z, bv.w);
                }
            }
        }
        // Recurrent part: h(t-1) @ Whh^T
        if (t > 0) {
#pragma unroll
            for (int ktp = 0; ktp < 4; ktp++) {
                const int cb = ktp * 16;
                unsigned a0[4], a1[4];
                a0[0] = *(const unsigned*)&h_s[cur][g    ][cb + tg    ];
                a0[1] = *(const unsigned*)&h_s[cur][g + 8][cb + tg    ];
                a0[2] = *(const unsigned*)&h_s[cur][g    ][cb + tg + 4];
                a0[3] = *(const unsigned*)&h_s[cur][g + 8][cb + tg + 4];
                a1[0] = *(const unsigned*)&h_s[cur][g    ][cb + 8 + tg    ];
                a1[1] = *(const unsigned*)&h_s[cur][g + 8][cb + 8 + tg    ];
                a1[2] = *(const unsigned*)&h_s[cur][g    ][cb + 8 + tg + 4];
                a1[3] = *(const unsigned*)&h_s[cur][g + 8][cb + 8 + tg + 4];
#pragma unroll
                for (int j = 0; j < 8; j++) {
                    if (j < ntn) {
                        uint4 bv = whh4[((nt0 + j) * 4 + ktp) * 32 + lane];
                        mma_f16(acc[j], a0, bv.x, bv.y);
                        mma_f16(acc[j], a1, bv.z, bv.w);
                    }
                }
            }
        }

        // Register-local pointwise cell update (gate order i, f, g, o).
#pragma unroll
        for (int jdb = 0; jdb < 2; jdb++) {
            if (jdb < dbn) {
                const int j0 = jdb * 4;
                const int d  = (db0 + jdb) * 8 + 2 * tg;
                float2 bq[4];
#pragma unroll
                for (int q = 0; q < 4; q++)
                    bq[q] = *(const float2*)&bias_s[q * DMODEL + d];
#pragma unroll
                for (int rs = 0; rs < 2; rs++) {
                    float h2v[2];
#pragma unroll
                    for (int cs = 0; cs < 2; cs++) {
                        const int v = rs * 2 + cs;
                        float gi = acc[j0 + 0][v] + (cs ? bq[0].y : bq[0].x);
                        float gf = acc[j0 + 1][v] + (cs ? bq[1].y : bq[1].x);
                        float gg = acc[j0 + 2][v] + (cs ? bq[2].y : bq[2].x);
                        float go = acc[j0 + 3][v] + (cs ? bq[3].y : bq[3].x);
                        const int ci = jdb * 4 + rs * 2 + cs;
                        float cn = sig_acc(gf) * c[ci] + sig_acc(gi) * tanh_acc(gg);
                        c[ci] = cn;
                        h2v[cs] = sig_acc(go) * tanh_acc(cn);
                    }
                    const int r = g + rs * 8;
                    __half2 hh = __floats2half2_rn(h2v[0], h2v[1]);
                    if (L0) {
                        *(__half2*)&hout_h[((size_t)(b0 + r) * SEQL + t) * DPAD + d] = hh;
                    } else {
                        *(float2*)&hout_f[((size_t)(b0 + r) * SEQL + t) * DMODEL + d] =
                            make_float2(h2v[0], h2v[1]);
                    }
                    h_s[nxt][r][d >> 1] = hh;
                }
            }
        }

        // Stage prefetched x(t+1).
        if (t < 15) {
            if (L0) {
#pragma unroll
                for (int i = 0; i < 2; i++) {
                    int flat = tid + 256 * i;
                    if (flat < ROWS * 30) {
                        int row = flat / 30, c4 = flat % 30;
                        x_s[nxt][row][c4 * 2]     = __floats2half2_rn(pxf[i].x, pxf[i].y);
                        x_s[nxt][row][c4 * 2 + 1] = __floats2half2_rn(pxf[i].z, pxf[i].w);
                    }
                }
            } else {
                int row = tid >> 4, u = tid & 15;
                *(uint4*)&x_s[nxt][row][u * 4] = pxh;
            }
        }
        __syncthreads();
    }
}

// ---------------------------------------------------------------------------
// fp16 tensor-core GEMM (logits): C[M,N] = A[M,128]h @ W[N,120]^T, fp32 acc.
// A is pre-quantized padded fp16 (LN output) -> raw uint4 loads, no cvt.
// Block tile 128x128, 256 thr / 8 warps. K=128 in 2 smem chunks of 64.
// ---------------------------------------------------------------------------
__global__ __launch_bounds__(256, 2)
void gemm_f16(const __half* __restrict__ A,
              const float* __restrict__ W,
              float* __restrict__ C, int N)
{
    __shared__ __half2 As2[128][36];
    __shared__ __half2 Ws2[128][36];

    const int tid  = threadIdx.x;
    const int wid  = tid >> 5;
    const int lane = tid & 31;
    const int g    = lane >> 2;
    const int tg   = lane & 3;
    const int m0   = blockIdx.x * 128;
    const int n0   = blockIdx.y * 128;
    const int wm   = wid >> 1;
    const int wn   = wid & 1;

    float acc[2][8][4];
#pragma unroll
    for (int mf = 0; mf < 2; mf++)
#pragma unroll
        for (int nf = 0; nf < 8; nf++)
#pragma unroll
            for (int i = 0; i < 4; i++) acc[mf][nf][i] = 0.0f;

#pragma unroll 1
    for (int ks = 0; ks < 2; ks++) {
        // A chunk: 128 rows x 8 uint4 = 1024 loads, 4/thread, no cvt.
#pragma unroll
        for (int i = 0; i < 4; i++) {
            int flat = tid + i * 256;
            int row = flat >> 3, u = flat & 7;
            uint4 v = *(const uint4*)(A + (size_t)(m0 + row) * DPAD + ks * 64 + u * 8);
            *(uint4*)&As2[row][u * 4] = v;
        }
        // W chunk (fp32 -> fp16, guards).
#pragma unroll
        for (int i = 0; i < 8; i++) {
            int flat = tid + i * 256;
            int row = flat >> 4, c4 = flat & 15;
            int k = ks * 64 + c4 * 4;
            float4 v = make_float4(0.f, 0.f, 0.f, 0.f);
            if (k < DMODEL && n0 + row < N)
                v = *(const float4*)(W + (size_t)(n0 + row) * DMODEL + k);
            Ws2[row][c4 * 2]     = __floats2half2_rn(v.x, v.y);
            Ws2[row][c4 * 2 + 1] = __floats2half2_rn(v.z, v.w);
        }
        __syncthreads();

#pragma unroll
        for (int kt = 0; kt < 4; kt++) {
            const int cb = kt * 8;
            unsigned a[2][4];
#pragma unroll
            for (int mf = 0; mf < 2; mf++) {
                int m = wm * 32 + mf * 16 + g;
                a[mf][0] = *(const unsigned*)&As2[m    ][cb + tg    ];
                a[mf][1] = *(const unsigned*)&As2[m + 8][cb + tg    ];
                a[mf][2] = *(const unsigned*)&As2[m    ][cb + tg + 4];
                a[mf][3] = *(const unsigned*)&As2[m + 8][cb + tg + 4];
            }
#pragma unroll
            for (int nf = 0; nf < 8; nf++) {
                int n = wn * 64 + nf * 8 + g;
                unsigned b0 = *(const unsigned*)&Ws2[n][cb + tg    ];
                unsigned b1 = *(const unsigned*)&Ws2[n][cb + tg + 4];
                mma_f16(acc[0][nf], a[0], b0, b1);
                mma_f16(acc[1][nf], a[1], b0, b1);
            }
        }
        __syncthreads();
    }

#pragma unroll
    for (int mf = 0; mf < 2; mf++) {
        const int m = m0 + wm * 32 + mf * 16 + g;
#pragma unroll
        for (int nf = 0; nf < 8; nf++) {
            const int n = n0 + wn * 64 + nf * 8 + 2 * tg;
            float* r0 = C + (size_t)m * N;
            float* r1 = C + (size_t)(m + 8) * N;
            if (n < N) {
                r0[n] = acc[mf][nf][0];
                r1[n] = acc[mf][nf][2];
            }
            if (n + 1 < N) {
                r0[n + 1] = acc[mf][nf][1];
                r1[n + 1] = acc[mf][nf][3];
            }
        }
    }
}

// ---------------------------------------------------------------------------
// LayerNorm over D=120: one warp per row (fp32 math), fp16 padded output
// (consumed only as logits-GEMM operand, which quantizes to fp16 anyway).
// Lane owns pairs d = 64*i + 2*lane -> half2 stores, pads 120..127 with 0.
// ---------------------------------------------------------------------------
__global__ __launch_bounds__(256)
void ln_k(const float* __restrict__ in,
          const float* __restrict__ gamma,
          const float* __restrict__ beta,
          __half* __restrict__ out)
{
    const int row  = blockIdx.x * 8 + (threadIdx.x >> 5);
    const int lane = threadIdx.x & 31;
    const float* rp = in + (size_t)row * DMODEL;

    float2 v[2];
    float s = 0.0f, s2 = 0.0f;
#pragma unroll
    for (int i = 0; i < 2; i++) {
        int d0 = 64 * i + 2 * lane;
        v[i] = (d0 < DMODEL) ? *(const float2*)(rp + d0) : make_float2(0.f, 0.f);
        s  += v[i].x + v[i].y;
        s2 += v[i].x * v[i].x + v[i].y * v[i].y;
    }
#pragma unroll
    for (int off = 16; off > 0; off >>= 1) {
        s  += __shfl_xor_sync(0xffffffffu, s,  off);
        s2 += __shfl_xor_sync(0xffffffffu, s2, off);
    }
    const float mu   = s  * (1.0f / DMODEL);
    const float var  = s2 * (1.0f / DMODEL) - mu * mu;
    const float rstd = rsqrtf(var + 1e-5f);

    __half* op = out + (size_t)row * DPAD;
#pragma unroll
    for (int i = 0; i < 2; i++) {
        int d0 = 64 * i + 2 * lane;
        __half2 hv = __floats2half2_rn(0.0f, 0.0f);
        if (d0 < DMODEL) {
            float2 gb = *(const float2*)(gamma + d0);
            float2 bb = *(const float2*)(beta + d0);
            hv = __floats2half2_rn((v[i].x - mu) * rstd * gb.x + bb.x,
                                   (v[i].y - mu) * rstd * gb.y + bb.y);
        }
        *(__half2*)&op[d0] = hv;
    }
}

// ---------------------------------------------------------------------------
extern "C" void kernel_launch(void* const* d_in, const int* in_sizes, int n_in,
                              void* d_out, int out_size)
{
    const int*   x     = (const int*)  d_in[0];
    const float* embed = (const float*)d_in[1];
    const float* Wih0  = (const float*)d_in[2];
    const float* Whh0  = (const float*)d_in[3];
    const float* bih0  = (const float*)d_in[4];
    const float* bhh0  = (const float*)d_in[5];
    const float* Wih1  = (const float*)d_in[6];
    const float* Whh1  = (const float*)d_in[7];
    const float* bih1  = (const float*)d_in[8];
    const float* bhh1  = (const float*)d_in[9];
    const float* gamma = (const float*)d_in[10];
    const float* beta  = (const float*)d_in[11];
    float* out = (float*)d_out;

    __half *h0, *lnh;
    float  *h1;
    uint4  *wpk;
    cudaGetSymbolAddress((void**)&h0,  g_h0);
    cudaGetSymbolAddress((void**)&h1,  g_h1);
    cudaGetSymbolAddress((void**)&lnh, g_lnh);
    cudaGetSymbolAddress((void**)&wpk, g_wpk);

    const int packGrid = (4 * NT_TILES * KT16 * 32 + 255) / 256;  // 240
    dim3 g433(MTOK / 128, (VOCAB + 127) / 128);  // (512, 4)

    // Pack all four weight matrices (fp16, kt-paired fragment layout).
    pack_wf16<<<packGrid, 256>>>(Wih0, Whh0, Wih1, Whh1, (unsigned*)wpk);

    // Layer 0: fused embed-gather + input GEMM + recurrence -> fp16 h0.
    lstm_fused<true ><<<BATCH / ROWS, 256>>>(nullptr, x, embed,
                                             wpk, wpk + WMAT_U4,
                                             bih0, bhh0, h0, nullptr);
    // Layer 1: fused (input = fp16 h0) -> fp32 h1.
    lstm_fused<false><<<BATCH / ROWS, 256>>>(h0, nullptr, nullptr,
                                             wpk + 2 * WMAT_U4, wpk + 3 * WMAT_U4,
                                             bih1, bhh1, nullptr, h1);
    // LayerNorm (fp32 math, fp16 padded output).
    ln_k<<<MTOK / 8, 256>>>(h1, gamma, beta, lnh);
    // Tied-embedding head: logits = ln @ embed^T.
    gemm_f16<<<g433, 256>>>(lnh, embed, out, VOCAB);
}